// round 13
// baseline (speedup 1.0000x reference)
#include <cuda_runtime.h>
#include <cstdint>

// OneHotEncoder: per-row token histogram (skip pad_idx=0) -> float counts.
// tokens: [B, T] int32, out: [B, 32000] float32.
//
// R13: minimal-aux design. R12 accounting: ATOMS drain ~= half the kernel,
// the rest was AUX (u16->f32 convert pass, staging STS, 17-barrier chain).
// Fix: f32 histogram that TMA bulk-stores DIRECTLY -> phases are just
//   prefetch -> zero -> bar -> atomics -> bar -> TMA commit+wait.
// SPLIT=2: 16000 bins = 64KB/CTA (no staging), 3 CTAs/SM, grid=512.
// 2x scan redundancy is trivial issue load (sub+cmp+predicated ATOMS).
// fp32 atomicAdd of +1 on integer-valued bins is exact. Pad check folded
// into the unsigned range check (+1 bias on slice 0) -> column 0 stays 0.

constexpr int VOCAB    = 32000;
constexpr int SPLIT    = 2;
constexpr int BINS     = VOCAB / SPLIT;     // 16000 floats = 64000 B
constexpr int NTHREADS = 512;

__global__ __launch_bounds__(NTHREADS, 3)
void onehot_hist_f32_tma_kernel(const int4* __restrict__ tokens4,
                                float* __restrict__ out,
                                int vecs_per_row)   // T/4 = 512
{
    extern __shared__ float hist[];   // BINS floats = 64000 B

    const int cta = blockIdx.x;
    const int s   = cta & (SPLIT - 1);       // vocab half
    const int b   = cta >> 1;                // row index
    const int lo  = s * BINS;
    const int tid = threadIdx.x;

    // Pad-fold: on slice 0 shift the window by 1 so t==0 fails the single
    // unsigned range check; bias the hist pointer back to compensate.
    const int      adj   = (s == 0) ? 1 : 0;
    const int      loAdj = lo + adj;
    const unsigned range = (unsigned)(BINS - adj);
    float* __restrict__ histAdj = hist + adj;

    // Front-batched token prefetch: 1 int4 per thread covers the row; the
    // L2 load latency hides behind the zero loop.
    const int4* __restrict__ trow = tokens4 + (size_t)b * vecs_per_row;
    int4 t = trow[tid];

    // Zero the histogram (4000 float4 over 512 threads).
    float4 z = make_float4(0.f, 0.f, 0.f, 0.f);
    #pragma unroll
    for (int i = tid; i < BINS / 4; i += NTHREADS) {
        reinterpret_cast<float4*>(hist)[i] = z;
    }
    __syncthreads();

    // Count: sub + unsigned cmp + predicated smem f32 atomic per token.
    {
        unsigned x;
        x = (unsigned)(t.x - loAdj); if (x < range) atomicAdd(&histAdj[x], 1.0f);
        x = (unsigned)(t.y - loAdj); if (x < range) atomicAdd(&histAdj[x], 1.0f);
        x = (unsigned)(t.z - loAdj); if (x < range) atomicAdd(&histAdj[x], 1.0f);
        x = (unsigned)(t.w - loAdj); if (x < range) atomicAdd(&histAdj[x], 1.0f);
    }
    __syncthreads();

    // One TMA 1-D bulk store writes the whole 64000B half-row to global.
    if (tid == 0) {
        asm volatile("fence.proxy.async.shared::cta;" ::: "memory");
        uint32_t saddr = (uint32_t)__cvta_generic_to_shared(hist);
        float* gdst = out + (size_t)b * VOCAB + lo;   // 16B-aligned halves
        asm volatile(
            "cp.async.bulk.global.shared::cta.bulk_group [%0], [%1], %2;"
            :: "l"(gdst), "r"(saddr), "r"((unsigned)(BINS * sizeof(float)))
            : "memory");
        asm volatile("cp.async.bulk.commit_group;" ::: "memory");
        asm volatile("cp.async.bulk.wait_group 0;" ::: "memory");
    }
}

extern "C" void kernel_launch(void* const* d_in, const int* in_sizes, int n_in,
                              void* d_out, int out_size)
{
    const int* tokens = (const int*)d_in[0];   // [B, T] int32
    // d_in[1] = lengths [B] int32 — unused by the reference computation.

    const int B = in_sizes[1];                 // 256
    const int T = in_sizes[0] / B;             // 2048

    float* out = (float*)d_out;                // [B, VOCAB] float32

    const int smem_bytes = BINS * (int)sizeof(float);  // 64000
    cudaFuncSetAttribute(onehot_hist_f32_tma_kernel,
                         cudaFuncAttributeMaxDynamicSharedMemorySize,
                         smem_bytes);
    cudaFuncSetAttribute(onehot_hist_f32_tma_kernel,
                         cudaFuncAttributePreferredSharedMemoryCarveout,
                         cudaSharedmemCarveoutMaxShared);

    onehot_hist_f32_tma_kernel<<<B * SPLIT, NTHREADS, smem_bytes>>>(
        (const int4*)tokens, out, T / 4);
}

// round 14
// speedup vs baseline: 1.0756x; 1.0756x over previous
#include <cuda_runtime.h>
#include <cstdint>

// OneHotEncoder: per-row token histogram (skip pad_idx=0) -> float counts.
// tokens: [B, T] int32, out: [B, 32000] float32.
//
// R14 = R13 with ONE change: the trailing TMA wait uses
//   cp.async.bulk.wait_group.read 0
// which completes as soon as the TMA engine has READ the smem histogram,
// instead of waiting for the 64KB global write to land in L2. R13's
// profile (no pipe above 35%, dur invariant ~9.5us across 10 designs)
// points at CTA lifetimes being serialized behind the full L2 store drain
// (~2.7us chip-wide) -> SMs idle in TMA-wait. With .read, CTAs retire as
// soon as smem is consumed and the global drain overlaps the next wave.
//
// Rest unchanged: f32 hist (fp32 +1 on integer bins is exact), SPLIT=2
// (16000 bins = 64KB/CTA, 3 CTAs/SM), front-batched token prefetch,
// pad check folded into the unsigned range check (+1 bias on slice 0),
// single TMA 1-D bulk store. Column 0 stays zero.

constexpr int VOCAB    = 32000;
constexpr int SPLIT    = 2;
constexpr int BINS     = VOCAB / SPLIT;     // 16000 floats = 64000 B
constexpr int NTHREADS = 512;

__global__ __launch_bounds__(NTHREADS, 3)
void onehot_hist_f32_tma_kernel(const int4* __restrict__ tokens4,
                                float* __restrict__ out,
                                int vecs_per_row)   // T/4 = 512
{
    extern __shared__ float hist[];   // BINS floats = 64000 B

    const int cta = blockIdx.x;
    const int s   = cta & (SPLIT - 1);       // vocab half
    const int b   = cta >> 1;                // row index
    const int lo  = s * BINS;
    const int tid = threadIdx.x;

    // Pad-fold: on slice 0 shift the window by 1 so t==0 fails the single
    // unsigned range check; bias the hist pointer back to compensate.
    const int      adj   = (s == 0) ? 1 : 0;
    const int      loAdj = lo + adj;
    const unsigned range = (unsigned)(BINS - adj);
    float* __restrict__ histAdj = hist + adj;

    // Front-batched token prefetch: 1 int4 per thread covers the row; the
    // L2 load latency hides behind the zero loop.
    const int4* __restrict__ trow = tokens4 + (size_t)b * vecs_per_row;
    int4 t = trow[tid];

    // Zero the histogram (4000 float4 over 512 threads).
    float4 z = make_float4(0.f, 0.f, 0.f, 0.f);
    #pragma unroll
    for (int i = tid; i < BINS / 4; i += NTHREADS) {
        reinterpret_cast<float4*>(hist)[i] = z;
    }
    __syncthreads();

    // Count: sub + unsigned cmp + predicated smem f32 atomic per token.
    {
        unsigned x;
        x = (unsigned)(t.x - loAdj); if (x < range) atomicAdd(&histAdj[x], 1.0f);
        x = (unsigned)(t.y - loAdj); if (x < range) atomicAdd(&histAdj[x], 1.0f);
        x = (unsigned)(t.z - loAdj); if (x < range) atomicAdd(&histAdj[x], 1.0f);
        x = (unsigned)(t.w - loAdj); if (x < range) atomicAdd(&histAdj[x], 1.0f);
    }
    __syncthreads();

    // One TMA 1-D bulk store writes the whole 64000B half-row to global.
    // Wait only until the SMEM side has been READ (.read) so the CTA can
    // retire while the global write drains in the background.
    if (tid == 0) {
        asm volatile("fence.proxy.async.shared::cta;" ::: "memory");
        uint32_t saddr = (uint32_t)__cvta_generic_to_shared(hist);
        float* gdst = out + (size_t)b * VOCAB + lo;   // 16B-aligned halves
        asm volatile(
            "cp.async.bulk.global.shared::cta.bulk_group [%0], [%1], %2;"
            :: "l"(gdst), "r"(saddr), "r"((unsigned)(BINS * sizeof(float)))
            : "memory");
        asm volatile("cp.async.bulk.commit_group;" ::: "memory");
        asm volatile("cp.async.bulk.wait_group.read 0;" ::: "memory");
    }
}

extern "C" void kernel_launch(void* const* d_in, const int* in_sizes, int n_in,
                              void* d_out, int out_size)
{
    const int* tokens = (const int*)d_in[0];   // [B, T] int32
    // d_in[1] = lengths [B] int32 — unused by the reference computation.

    const int B = in_sizes[1];                 // 256
    const int T = in_sizes[0] / B;             // 2048

    float* out = (float*)d_out;                // [B, VOCAB] float32

    const int smem_bytes = BINS * (int)sizeof(float);  // 64000
    cudaFuncSetAttribute(onehot_hist_f32_tma_kernel,
                         cudaFuncAttributeMaxDynamicSharedMemorySize,
                         smem_bytes);
    cudaFuncSetAttribute(onehot_hist_f32_tma_kernel,
                         cudaFuncAttributePreferredSharedMemoryCarveout,
                         cudaSharedmemCarveoutMaxShared);

    onehot_hist_f32_tma_kernel<<<B * SPLIT, NTHREADS, smem_bytes>>>(
        (const int4*)tokens, out, T / 4);
}